// round 9
// baseline (speedup 1.0000x reference)
#include <cuda_runtime.h>
#include <cstdint>
#include <cstddef>

#define BATCHN 10
#define HID    128
#define OUTD   7
#define TLEN   2048
#define TPB    256      // 2 CTAs per batch; thread = one full gate row (ty,k)
#define KPC    64       // hidden units owned per CTA

typedef unsigned long long ull;

__device__ __forceinline__ uint32_t sm2u(const void* p) {
    return (uint32_t)__cvta_generic_to_shared(const_cast<void*>(p));
}
__device__ __forceinline__ uint32_t ctarank() {
    uint32_t r; asm("mov.u32 %0, %%cluster_ctarank;" : "=r"(r)); return r;
}
__device__ __forceinline__ void dst_f32(uint32_t saddr, uint32_t rk, float v) {
    uint32_t ra;
    asm volatile("mapa.shared::cluster.u32 %0, %1, %2;" : "=r"(ra) : "r"(saddr), "r"(rk));
    asm volatile("st.shared::cluster.f32 [%0], %1;" :: "r"(ra), "f"(v) : "memory");
}
__device__ __forceinline__ ull fma2(ull a, ull b, ull c) {
    ull d; asm("fma.rn.f32x2 %0, %1, %2, %3;" : "=l"(d) : "l"(a), "l"(b), "l"(c)); return d;
}
__device__ __forceinline__ ull pk2(float lo, float hi) {
    ull r; asm("mov.b64 %0, {%1, %2};" : "=l"(r) : "f"(lo), "f"(hi)); return r;
}
__device__ __forceinline__ float2 unpk2(ull v) {
    float2 f; asm("mov.b64 {%0, %1}, %2;" : "=f"(f.x), "=f"(f.y) : "l"(v)); return f;
}
__device__ __forceinline__ float fsig(float x)  { return __fdividef(1.f, 1.f + __expf(-x)); }
__device__ __forceinline__ float ftanh(float x) { return 2.f * __fdividef(1.f, 1.f + __expf(-2.f * x)) - 1.f; }

#define CLU_ARRIVE() asm volatile("barrier.cluster.arrive.aligned;" ::: "memory")
#define CLU_WAIT()   asm volatile("barrier.cluster.wait.aligned;"   ::: "memory")
#define FULLM 0xffffffffu

// 2-CTA cluster per batch; all W_hh in registers. Split-phase pipeline:
// own-half dot runs BEFORE the cluster wait; peer-half dot after.
__global__ void __cluster_dims__(2, 1, 1) __launch_bounds__(TPB, 1)
lstm_decoder_kernel(const float* __restrict__ h0,
                    const float* __restrict__ c0,
                    const float* __restrict__ tonehot,   // (TLEN+1, 1, OUTD)
                    const void*  __restrict__ tfraw,     // tf_mask (dtype autodetect)
                    const float* __restrict__ W_ih,      // (4*HID, OUTD)
                    const float* __restrict__ W_hh,      // (4*HID, HID)
                    const float* __restrict__ b_ih,
                    const float* __restrict__ b_hh,
                    const float* __restrict__ W_out,     // (OUTD, HID)
                    const float* __restrict__ b_out,
                    float* __restrict__ out)             // [143360 lp | 1280 hT | 1280 cT]
{
    __shared__ __align__(16) float h_s[2][HID];     // full h per CTA, parity buffered
    __shared__ float plog_s[2][16][8];              // warp logit partials: slot = rank*8+wid
    __shared__ float wih_s[4 * HID * OUTD];
    __shared__ int   tgt_s[TLEN];
    __shared__ unsigned char tf_s[TLEN];
    __shared__ float bout_s[OUTD];
    __shared__ int   tfmode_s;

    const int b    = blockIdx.x >> 1;    // batch
    const uint32_t rank = ctarank();     // 0 or 1
    const uint32_t peer = rank ^ 1u;
    const int tid  = threadIdx.x;
    const int lane = tid & 31;
    const int wid  = tid >> 5;           // 0..7
    const int ty   = tid & 3;            // gate type 0=i 1=f 2=g 3=o
    const int kl   = tid >> 2;           // local unit 0..63
    const int k    = (int)rank * KPC + kl;   // global hidden unit
    const int g    = ty * HID + k;           // gate row

    // Full W_hh row g in registers: 64 packed u64 (128 regs)
    ull wp[HID / 2];
#pragma unroll
    for (int i = 0; i < HID / 4; i++) {
        float4 v = reinterpret_cast<const float4*>(W_hh + (size_t)g * HID)[i];
        wp[2*i]   = pk2(v.x, v.y);
        wp[2*i+1] = pk2(v.z, v.w);
    }
    const float biasg = b_ih[g] + b_hh[g];
    const int   gbase = g * OUTD;
    const int   wown  = (int)rank * 32;      // wp index base for own 64 cols
    const int   wpeer = (int)peer * 32;      // wp index base for peer 64 cols

    const float wo1 = W_out[ty * HID + k];
    const float wo2 = (ty < 3) ? W_out[(ty + 4) * HID + k] : 0.f;

    float cval = c0[b * HID + k];

    // ---- init ----
    if (tid < HID) h_s[0][tid] = h0[b * HID + tid];
    for (int i = tid; i < 4 * HID * OUTD; i += TPB) wih_s[i] = W_ih[i];
    if (tid < OUTD) bout_s[tid] = b_out[tid];
    if (tid == 0) {                                   // tf dtype autodetect
        const int* ip = (const int*)tfraw;
        int mode = 0;
        for (int i = 0; i < 512; i++) {
            int v = ip[i];
            if (v == 0x3f800000) { mode = 1; break; }
            if (v != 0 && v != 1) mode = 2;
        }
        tfmode_s = mode;
    }
    __syncthreads();
    {
        const int mode = tfmode_s;
        for (int s = tid; s < TLEN; s += TPB) {
            unsigned char tv;
            if (mode == 0)      tv = ((const int*)tfraw)[s] != 0;
            else if (mode == 1) tv = ((const float*)tfraw)[s] != 0.f;
            else                tv = ((const unsigned char*)tfraw)[s] != 0;
            tf_s[s] = tv;
            const float* row = tonehot + (size_t)(s + 1) * OUTD;   // exactly one-hot
            int idx = 0; float best = row[0];
#pragma unroll
            for (int o = 1; o < OUTD; o++) { if (row[o] > best) { best = row[o]; idx = o; } }
            tgt_s[s] = idx;
        }
    }
    __syncthreads();
    CLU_ARRIVE(); CLU_WAIT();    // init visible cluster-wide
    CLU_ARRIVE();                // arrive #0 (paired by the wait inside iteration 0)

    // ================= main loop =================
    for (int t = 0; t < TLEN; t++) {
        const int p = t & 1;

        // ---- Phase A: dot over OWN 64 columns (local data; pre-wait) ----
        ull accA = 0ull, accB = 0ull;
        {
            const ulonglong2* ho = reinterpret_cast<const ulonglong2*>(&h_s[p][rank * KPC]);
#pragma unroll
            for (int i = 0; i < 8; i++) {
                ulonglong2 u = ho[2*i];
                ulonglong2 v = ho[2*i + 1];
                accA = fma2(u.x, wp[wown + 4*i],     accA);
                accB = fma2(u.y, wp[wown + 4*i + 1], accB);
                accA = fma2(v.x, wp[wown + 4*i + 2], accA);
                accB = fma2(v.y, wp[wown + 4*i + 3], accB);
            }
        }

        // ---- Phase B: wait for peer h-half + plog ----
        CLU_WAIT();

        // ---- Phase C1: dot over PEER 64 columns ----
        ull accC = 0ull, accD = 0ull;
        {
            const ulonglong2* hp = reinterpret_cast<const ulonglong2*>(&h_s[p][peer * KPC]);
#pragma unroll
            for (int i = 0; i < 8; i++) {
                ulonglong2 u = hp[2*i];
                ulonglong2 v = hp[2*i + 1];
                accC = fma2(u.x, wp[wpeer + 4*i],     accC);
                accD = fma2(u.y, wp[wpeer + 4*i + 1], accD);
                accC = fma2(v.x, wp[wpeer + 4*i + 2], accC);
                accD = fma2(v.y, wp[wpeer + 4*i + 3], accD);
            }
        }

        // ---- argmax of logits(t-1) ----
        int xb = OUTD - 1;
        float slog = -1e30f, vmax = -1e30f;
        if (t > 0) {
            const int o = lane & 7;
            float s = -1e30f;
            if (lane < 8 && o < OUTD) {
                const float* pp = &plog_s[p][0][o];
                float s0 = pp[0*8]  + pp[1*8];
                float s1 = pp[2*8]  + pp[3*8];
                float s2 = pp[4*8]  + pp[5*8];
                float s3 = pp[6*8]  + pp[7*8];
                float s4 = pp[8*8]  + pp[9*8];
                float s5 = pp[10*8] + pp[11*8];
                float s6 = pp[12*8] + pp[13*8];
                float s7 = pp[14*8] + pp[15*8];
                s = bout_s[o] + (((s0+s1)+(s2+s3)) + ((s4+s5)+(s6+s7)));
            }
            float v = s;
            int   idx = (lane < 8 && o < OUTD) ? o : OUTD;
#pragma unroll
            for (int d = 4; d >= 1; d >>= 1) {
                float v2 = __shfl_xor_sync(FULLM, v, d, 8);
                int   i2 = __shfl_xor_sync(FULLM, idx, d, 8);
                if (v2 > v || (v2 == v && i2 < idx)) { v = v2; idx = i2; }
            }
            slog = s; vmax = v;
            const int ia = __shfl_sync(FULLM, idx, 0);
            xb = tf_s[t - 1] ? tgt_s[t - 1] : ia;
        }

        // ---- finish gate (combine halves in fixed order: cols 0..63 + cols 64..127) ----
        ull accLo = (rank == 0) ? accA : accC;   // cols 0..63 accumulator pair
        ull accLo2= (rank == 0) ? accB : accD;
        ull accHi = (rank == 0) ? accC : accA;   // cols 64..127
        ull accHi2= (rank == 0) ? accD : accB;
        float2 f0 = unpk2(accLo), f1 = unpk2(accLo2), f2 = unpk2(accHi), f3 = unpk2(accHi2);
        float vb = ((f0.x + f0.y) + (f1.x + f1.y)) + ((f2.x + f2.y) + (f3.x + f3.y))
                 + biasg + wih_s[gbase + xb];
        vb = (ty == 2) ? ftanh(vb) : fsig(vb);

        // ---- quad butterfly: every lane gets (i,f,g,o) of its unit ----
        const float pb1 = __shfl_xor_sync(FULLM, vb, 1, 4);
        const float ev  = (ty & 1) ? pb1 : vb;
        const float od  = (ty & 1) ? vb  : pb1;
        const float ev2 = __shfl_xor_sync(FULLM, ev, 2, 4);
        const float od2 = __shfl_xor_sync(FULLM, od, 2, 4);
        const float gi = (ty & 2) ? ev2 : ev;
        const float gf = (ty & 2) ? od2 : od;
        const float gg = (ty & 2) ? ev  : ev2;
        const float go = (ty & 2) ? od  : od2;

        // ---- pointwise (redundant x4 per unit) ----
        cval = gf * cval + gi * gg;
        const float h2 = go * ftanh(cval);
        if (ty == 0) {
            h_s[p ^ 1][k] = h2;                        // local copy (own half)
            dst_f32(sm2u(&h_s[p ^ 1][k]), peer, h2);   // peer copy
        }

        // ---- logit partials over the warp's 8 units ----
        float pl1 = h2 * wo1;
        float pl2 = h2 * wo2;
#pragma unroll
        for (int d = 4; d <= 16; d <<= 1) {
            pl1 += __shfl_xor_sync(FULLM, pl1, d);
            pl2 += __shfl_xor_sync(FULLM, pl2, d);
        }
        if (lane < 4) {
            const int slot = (int)rank * 8 + wid;
            plog_s[p ^ 1][slot][ty] = pl1;
            dst_f32(sm2u(&plog_s[p ^ 1][slot][ty]), peer, pl1);
            if (ty < 3) {
                plog_s[p ^ 1][slot][ty + 4] = pl2;
                dst_f32(sm2u(&plog_s[p ^ 1][slot][ty + 4]), peer, pl2);
            }
        }

        // ---- arrive; softmax(t-1)+STG inside the window; local sync for phase A ----
        CLU_ARRIVE();
        if (t > 0 && rank == 0 && wid == 7) {
            const int o = lane & 7;
            float e = (lane < 8 && o < OUTD) ? __expf(slog - vmax) : 0.f;
#pragma unroll
            for (int d = 4; d >= 1; d >>= 1)
                e += __shfl_xor_sync(FULLM, e, d, 8);
            const float lse = vmax + __logf(e);
            if (lane < OUTD)
                out[(size_t)b * TLEN * OUTD + (size_t)(t - 1) * OUTD + lane] = slog - lse;
        }
        __syncthreads();   // local h2 (own half) visible for next phase A
    }

    // ================= epilogue =================
    CLU_WAIT();            // pairs with the last loop arrive; last plog/h valid
    {
        const int o = lane & 7;
        float s = -1e30f;
        if (lane < 8 && o < OUTD) {
            const float* pp = &plog_s[0][0][o];
            float acc = bout_s[o];
#pragma unroll
            for (int w2 = 0; w2 < 16; w2++) acc += pp[w2 * 8];
            s = acc;
        }
        float v = s;
#pragma unroll
        for (int d = 4; d >= 1; d >>= 1) {
            float v2 = __shfl_xor_sync(FULLM, v, d, 8);
            if (v2 > v) v = v2;
        }
        float e = (lane < 8 && o < OUTD) ? __expf(s - v) : 0.f;
#pragma unroll
        for (int d = 4; d >= 1; d >>= 1)
            e += __shfl_xor_sync(FULLM, e, d, 8);
        const float lse = v + __logf(e);
        if (rank == 0 && wid == 7 && lane < OUTD)
            out[(size_t)b * TLEN * OUTD + (size_t)(TLEN - 1) * OUTD + lane] = s - lse;

        if (rank == 0) {
            for (int i = tid; i < HID; i += TPB)
                out[(size_t)BATCHN * TLEN * OUTD + b * HID + i] = h_s[0][i];
        }
        if (ty == 0)
            out[(size_t)BATCHN * TLEN * OUTD + BATCHN * HID + b * HID + k] = cval;
    }
    CLU_ARRIVE(); CLU_WAIT();   // keep cluster alive until peer DSMEM traffic done
}

extern "C" void kernel_launch(void* const* d_in, const int* in_sizes, int n_in,
                              void* d_out, int out_size) {
    (void)in_sizes; (void)n_in; (void)out_size;
    const float* h0    = (const float*)d_in[0];
    const float* c0    = (const float*)d_in[1];
    const float* toh   = (const float*)d_in[2];
    const void*  tf    = d_in[3];
    const float* W_ih  = (const float*)d_in[4];
    const float* W_hh  = (const float*)d_in[5];
    const float* b_ih  = (const float*)d_in[6];
    const float* b_hh  = (const float*)d_in[7];
    const float* W_out = (const float*)d_in[8];
    const float* b_out = (const float*)d_in[9];
    float* out = (float*)d_out;

    lstm_decoder_kernel<<<2 * BATCHN, TPB>>>(h0, c0, toh, tf, W_ih, W_hh,
                                             b_ih, b_hh, W_out, b_out, out);
}

// round 10
// speedup vs baseline: 1.2295x; 1.2295x over previous
#include <cuda_runtime.h>
#include <cstdint>
#include <cstddef>

#define BATCHN 10
#define HID    128
#define OUTD   7
#define TLEN   2048
#define TPB    256      // 2 CTAs per batch; thread = one full gate row (ty,k)
#define KPC    64       // hidden units owned per CTA

typedef unsigned long long ull;

__device__ __forceinline__ uint32_t sm2u(const void* p) {
    return (uint32_t)__cvta_generic_to_shared(const_cast<void*>(p));
}
__device__ __forceinline__ uint32_t ctarank() {
    uint32_t r; asm("mov.u32 %0, %%cluster_ctarank;" : "=r"(r)); return r;
}
__device__ __forceinline__ void dst_u64(uint32_t saddr, uint32_t rk, ull v) {
    uint32_t ra;
    asm volatile("mapa.shared::cluster.u32 %0, %1, %2;" : "=r"(ra) : "r"(saddr), "r"(rk));
    asm volatile("st.shared::cluster.b64 [%0], %1;" :: "r"(ra), "l"(v) : "memory");
}
__device__ __forceinline__ void dst_f32(uint32_t saddr, uint32_t rk, float v) {
    uint32_t ra;
    asm volatile("mapa.shared::cluster.u32 %0, %1, %2;" : "=r"(ra) : "r"(saddr), "r"(rk));
    asm volatile("st.shared::cluster.f32 [%0], %1;" :: "r"(ra), "f"(v) : "memory");
}
// release-scope-cluster arrive on LOCAL mbarrier
__device__ __forceinline__ void mbar_arrive_local(uint32_t mb) {
    asm volatile("mbarrier.arrive.release.cluster.shared::cta.b64 _, [%0];" :: "r"(mb) : "memory");
}
// release-scope-cluster arrive on PEER CTA's mbarrier
__device__ __forceinline__ void mbar_arrive_remote(uint32_t mb, uint32_t rk) {
    uint32_t ra;
    asm volatile("mapa.shared::cluster.u32 %0, %1, %2;" : "=r"(ra) : "r"(mb), "r"(rk));
    asm volatile("mbarrier.arrive.release.cluster.shared::cluster.b64 _, [%0];" :: "r"(ra) : "memory");
}
#define MBAR_WAIT(addr, par) do {                                                        \
    asm volatile("{\n\t.reg .pred P1;\n\t"                                               \
        "WL%=:\n\t"                                                                      \
        "mbarrier.try_wait.parity.acquire.cluster.shared::cta.b64 P1, [%0], %1, 0x989680;\n\t" \
        "@P1 bra WD%=;\n\t bra WL%=;\n\tWD%=:\n\t}"                                      \
        :: "r"(addr), "r"(par) : "memory");                                              \
} while (0)

__device__ __forceinline__ ull fma2(ull a, ull b, ull c) {
    ull d; asm("fma.rn.f32x2 %0, %1, %2, %3;" : "=l"(d) : "l"(a), "l"(b), "l"(c)); return d;
}
__device__ __forceinline__ ull pk2(float lo, float hi) {
    ull r; asm("mov.b64 %0, {%1, %2};" : "=l"(r) : "f"(lo), "f"(hi)); return r;
}
__device__ __forceinline__ float2 unpk2(ull v) {
    float2 f; asm("mov.b64 {%0, %1}, %2;" : "=f"(f.x), "=f"(f.y) : "l"(v)); return f;
}
__device__ __forceinline__ float fsig(float x)  { return __fdividef(1.f, 1.f + __expf(-x)); }
__device__ __forceinline__ float ftanh(float x) { return 2.f * __fdividef(1.f, 1.f + __expf(-2.f * x)) - 1.f; }

#define CLU_ARRIVE() asm volatile("barrier.cluster.arrive.aligned;" ::: "memory")
#define CLU_WAIT()   asm volatile("barrier.cluster.wait.aligned;"   ::: "memory")
#define FULLM 0xffffffffu

// 2-CTA cluster per batch; all W_hh register-resident. Step sync = 2-count
// mbarrier (tid0 arrives local+remote after __syncthreads); REDUX argmax.
__global__ void __cluster_dims__(2, 1, 1) __launch_bounds__(TPB, 1)
lstm_decoder_kernel(const float* __restrict__ h0,
                    const float* __restrict__ c0,
                    const float* __restrict__ tonehot,   // (TLEN+1, 1, OUTD)
                    const void*  __restrict__ tfraw,     // tf_mask (dtype autodetect)
                    const float* __restrict__ W_ih,      // (4*HID, OUTD)
                    const float* __restrict__ W_hh,      // (4*HID, HID)
                    const float* __restrict__ b_ih,
                    const float* __restrict__ b_hh,
                    const float* __restrict__ W_out,     // (OUTD, HID)
                    const float* __restrict__ b_out,
                    float* __restrict__ out)             // [143360 lp | 1280 hT | 1280 cT]
{
    __shared__ __align__(16) float h_s[2][HID];     // full h per CTA, parity buffered
    __shared__ float plog_s[2][16][8];              // warp logit partials: slot = rank*8+wid
    __shared__ float wih_s[4 * HID * OUTD];
    __shared__ int   tgt_s[TLEN];
    __shared__ unsigned char tf_s[TLEN];
    __shared__ float bout_s[OUTD];
    __shared__ int   tfmode_s;
    __shared__ __align__(8) ull mbar_s;

    const int b    = blockIdx.x >> 1;    // batch
    const uint32_t rank = ctarank();     // 0 or 1
    const uint32_t peer = rank ^ 1u;
    const int tid  = threadIdx.x;
    const int lane = tid & 31;
    const int wid  = tid >> 5;           // 0..7
    const int ty   = tid & 3;            // gate type 0=i 1=f 2=g 3=o
    const int kl   = tid >> 2;           // local unit 0..63
    const int k    = (int)rank * KPC + kl;   // global hidden unit
    const int g    = ty * HID + k;           // gate row
    const uint32_t mb = sm2u(&mbar_s);

    // Full W_hh row g in registers: 64 packed u64 (128 regs)
    ull wp[HID / 2];
#pragma unroll
    for (int i = 0; i < HID / 4; i++) {
        float4 v = reinterpret_cast<const float4*>(W_hh + (size_t)g * HID)[i];
        wp[2*i]   = pk2(v.x, v.y);
        wp[2*i+1] = pk2(v.z, v.w);
    }
    const float biasg = b_ih[g] + b_hh[g];
    const int   gbase = g * OUTD;

    const float wo1 = W_out[ty * HID + k];
    const float wo2 = (ty < 3) ? W_out[(ty + 4) * HID + k] : 0.f;

    float cval = c0[b * HID + k];

    // ---- init ----
    if (tid == 0)
        asm volatile("mbarrier.init.shared.b64 [%0], %1;" :: "r"(mb), "r"(2) : "memory");
    if (tid < HID) h_s[0][tid] = h0[b * HID + tid];
    for (int i = tid; i < 4 * HID * OUTD; i += TPB) wih_s[i] = W_ih[i];
    if (tid < OUTD) bout_s[tid] = b_out[tid];
    if (tid == 0) {                                   // tf dtype autodetect
        const int* ip = (const int*)tfraw;
        int mode = 0;
        for (int i = 0; i < 512; i++) {
            int v = ip[i];
            if (v == 0x3f800000) { mode = 1; break; }
            if (v != 0 && v != 1) mode = 2;
        }
        tfmode_s = mode;
    }
    __syncthreads();
    {
        const int mode = tfmode_s;
        for (int s = tid; s < TLEN; s += TPB) {
            unsigned char tv;
            if (mode == 0)      tv = ((const int*)tfraw)[s] != 0;
            else if (mode == 1) tv = ((const float*)tfraw)[s] != 0.f;
            else                tv = ((const unsigned char*)tfraw)[s] != 0;
            tf_s[s] = tv;
            const float* row = tonehot + (size_t)(s + 1) * OUTD;   // exactly one-hot
            int idx = 0; float best = row[0];
#pragma unroll
            for (int o = 1; o < OUTD; o++) { if (row[o] > best) { best = row[o]; idx = o; } }
            tgt_s[s] = idx;
        }
    }
    __syncthreads();
    CLU_ARRIVE(); CLU_WAIT();    // smem init + mbarrier init visible cluster-wide

    // ================= main loop =================
    for (int t = 0; t < TLEN; t++) {
        const int p = t & 1;

        // ---- recurrent dot: all 128 cols, weights in regs, h broadcast-LDS ----
        ull acc0 = 0ull, acc1 = 0ull, acc2 = 0ull, acc3 = 0ull;
        const ulonglong2* hb = reinterpret_cast<const ulonglong2*>(h_s[p]);
#pragma unroll
        for (int i = 0; i < 16; i++) {
            ulonglong2 u = hb[2*i];
            ulonglong2 v = hb[2*i + 1];
            acc0 = fma2(u.x, wp[4*i],     acc0);
            acc1 = fma2(u.y, wp[4*i + 1], acc1);
            acc2 = fma2(v.x, wp[4*i + 2], acc2);
            acc3 = fma2(v.y, wp[4*i + 3], acc3);
        }

        // ---- argmax of logits(t-1) via single REDUX (exact, tie -> smallest idx) ----
        int xb = OUTD - 1;
        float slog = -1e30f, vmax = -1e30f;
        if (t > 0) {
            const int o = lane & 7;
            float s = -1e30f;
            uint32_t enc = 0;
            if (lane < 8 && o < OUTD) {
                const float* pp = &plog_s[p][0][o];
                float s0 = pp[0*8]  + pp[1*8];
                float s1 = pp[2*8]  + pp[3*8];
                float s2 = pp[4*8]  + pp[5*8];
                float s3 = pp[6*8]  + pp[7*8];
                float s4 = pp[8*8]  + pp[9*8];
                float s5 = pp[10*8] + pp[11*8];
                float s6 = pp[12*8] + pp[13*8];
                float s7 = pp[14*8] + pp[15*8];
                s = bout_s[o] + (((s0+s1)+(s2+s3)) + ((s4+s5)+(s6+s7)));
                // |s| <= ~12  ->  s+32 in (20,44): exponent field >= 0x40000000
                enc = ((__float_as_uint(s + 32.0f) - 0x40000000u) << 3) | (uint32_t)(7 - o);
            }
            const uint32_t m = __reduce_max_sync(FULLM, enc);
            const int ia = 7 - (int)(m & 7u);
            vmax = __uint_as_float((m >> 3) + 0x40000000u) - 32.0f;
            slog = s;
            xb = tf_s[t - 1] ? tgt_s[t - 1] : ia;
        }

        // ---- finish gate ----
        float2 f0 = unpk2(acc0), f1 = unpk2(acc1), f2 = unpk2(acc2), f3 = unpk2(acc3);
        float vb = ((f0.x + f0.y) + (f1.x + f1.y)) + ((f2.x + f2.y) + (f3.x + f3.y))
                 + biasg + wih_s[gbase + xb];
        vb = (ty == 2) ? ftanh(vb) : fsig(vb);

        // ---- quad butterfly: every lane gets (i,f,g,o) of its unit ----
        const float pb1 = __shfl_xor_sync(FULLM, vb, 1, 4);
        const float ev  = (ty & 1) ? pb1 : vb;
        const float od  = (ty & 1) ? vb  : pb1;
        const float ev2 = __shfl_xor_sync(FULLM, ev, 2, 4);
        const float od2 = __shfl_xor_sync(FULLM, od, 2, 4);
        const float gi = (ty & 2) ? ev2 : ev;
        const float gf = (ty & 2) ? od2 : od;
        const float gg = (ty & 2) ? ev  : ev2;
        const float go = (ty & 2) ? od  : od2;

        // ---- pointwise (redundant x4 per unit) ----
        cval = gf * cval + gi * gg;
        const float h2 = go * ftanh(cval);

        // ---- h publish: packed 8B, local plain + peer DSMEM ----
        const float h2hi = __shfl_xor_sync(FULLM, h2, 4);   // partner unit (k^1) lives 4 lanes away
        if ((tid & 7) == 0) {                               // ty==0 and k even
            const ull hv = pk2(h2, h2hi);
            *reinterpret_cast<ull*>(&h_s[p ^ 1][k]) = hv;
            dst_u64(sm2u(&h_s[p ^ 1][k]), peer, hv);
        }

        // ---- logit partials over the warp's 8 units ----
        float pl1 = h2 * wo1;
        float pl2 = h2 * wo2;
#pragma unroll
        for (int d = 4; d <= 16; d <<= 1) {
            pl1 += __shfl_xor_sync(FULLM, pl1, d);
            pl2 += __shfl_xor_sync(FULLM, pl2, d);
        }
        if (lane < 4) {
            const int slot = (int)rank * 8 + wid;
            plog_s[p ^ 1][slot][ty] = pl1;
            dst_f32(sm2u(&plog_s[p ^ 1][slot][ty]), peer, pl1);
            if (ty < 3) {
                plog_s[p ^ 1][slot][ty + 4] = pl2;
                dst_f32(sm2u(&plog_s[p ^ 1][slot][ty + 4]), peer, pl2);
            }
        }

        // ---- sync: CTA barrier -> 2 release-arrives -> softmax in window -> wait ----
        __syncthreads();
        if (tid == 0) {
            mbar_arrive_local(mb);
            mbar_arrive_remote(mb, peer);
        }
        if (t > 0 && rank == 0 && wid == 7) {
            const int o = lane & 7;
            float e = (lane < 8 && o < OUTD) ? __expf(slog - vmax) : 0.f;
#pragma unroll
            for (int d = 4; d >= 1; d >>= 1)
                e += __shfl_xor_sync(FULLM, e, d, 8);
            const float lse = vmax + __logf(e);
            if (lane < OUTD)
                out[(size_t)b * TLEN * OUTD + (size_t)(t - 1) * OUTD + lane] = slog - lse;
        }
        MBAR_WAIT(mb, p);
    }

    // ================= epilogue =================
    {
        const int o = lane & 7;
        float s = -1e30f;
        if (lane < 8 && o < OUTD) {
            const float* pp = &plog_s[0][0][o];
            float acc = bout_s[o];
#pragma unroll
            for (int w2 = 0; w2 < 16; w2++) acc += pp[w2 * 8];
            s = acc;
        }
        float v = s;
#pragma unroll
        for (int d = 4; d >= 1; d >>= 1) {
            float v2 = __shfl_xor_sync(FULLM, v, d, 8);
            if (v2 > v) v = v2;
        }
        float e = (lane < 8 && o < OUTD) ? __expf(s - v) : 0.f;
#pragma unroll
        for (int d = 4; d >= 1; d >>= 1)
            e += __shfl_xor_sync(FULLM, e, d, 8);
        const float lse = v + __logf(e);
        if (rank == 0 && wid == 7 && lane < OUTD)
            out[(size_t)b * TLEN * OUTD + (size_t)(TLEN - 1) * OUTD + lane] = s - lse;

        if (rank == 0) {
            for (int i = tid; i < HID; i += TPB)
                out[(size_t)BATCHN * TLEN * OUTD + b * HID + i] = h_s[0][i];
        }
        if (ty == 0)
            out[(size_t)BATCHN * TLEN * OUTD + BATCHN * HID + b * HID + k] = cval;
    }
    // keep cluster alive until all peer-targeted DSMEM traffic is consumed
    CLU_ARRIVE(); CLU_WAIT();
}

extern "C" void kernel_launch(void* const* d_in, const int* in_sizes, int n_in,
                              void* d_out, int out_size) {
    (void)in_sizes; (void)n_in; (void)out_size;
    const float* h0    = (const float*)d_in[0];
    const float* c0    = (const float*)d_in[1];
    const float* toh   = (const float*)d_in[2];
    const void*  tf    = d_in[3];
    const float* W_ih  = (const float*)d_in[4];
    const float* W_hh  = (const float*)d_in[5];
    const float* b_ih  = (const float*)d_in[6];
    const float* b_hh  = (const float*)d_in[7];
    const float* W_out = (const float*)d_in[8];
    const float* b_out = (const float*)d_in[9];
    float* out = (float*)d_out;

    lstm_decoder_kernel<<<2 * BATCHN, TPB>>>(h0, c0, toh, tf, W_ih, W_hh,
                                             b_ih, b_hh, W_out, b_out, out);
}

// round 11
// speedup vs baseline: 1.5048x; 1.2238x over previous
#include <cuda_runtime.h>
#include <cstdint>
#include <cstddef>

#define BATCHN 10
#define HID    128
#define OUTD   7
#define TLEN   2048
#define TPB    256      // 2 CTAs per batch; thread = one full gate row (ty,k)
#define KPC    64       // hidden units owned per CTA

typedef unsigned long long ull;

__device__ __forceinline__ uint32_t sm2u(const void* p) {
    return (uint32_t)__cvta_generic_to_shared(const_cast<void*>(p));
}
__device__ __forceinline__ uint32_t ctarank() {
    uint32_t r; asm("mov.u32 %0, %%cluster_ctarank;" : "=r"(r)); return r;
}
__device__ __forceinline__ void dst_u64(uint32_t saddr, uint32_t rk, ull v) {
    uint32_t ra;
    asm volatile("mapa.shared::cluster.u32 %0, %1, %2;" : "=r"(ra) : "r"(saddr), "r"(rk));
    asm volatile("st.shared::cluster.b64 [%0], %1;" :: "r"(ra), "l"(v) : "memory");
}
__device__ __forceinline__ void dst_f32(uint32_t saddr, uint32_t rk, float v) {
    uint32_t ra;
    asm volatile("mapa.shared::cluster.u32 %0, %1, %2;" : "=r"(ra) : "r"(saddr), "r"(rk));
    asm volatile("st.shared::cluster.f32 [%0], %1;" :: "r"(ra), "f"(v) : "memory");
}
__device__ __forceinline__ ull fma2(ull a, ull b, ull c) {
    ull d; asm("fma.rn.f32x2 %0, %1, %2, %3;" : "=l"(d) : "l"(a), "l"(b), "l"(c)); return d;
}
__device__ __forceinline__ ull pk2(float lo, float hi) {
    ull r; asm("mov.b64 %0, {%1, %2};" : "=l"(r) : "f"(lo), "f"(hi)); return r;
}
__device__ __forceinline__ float2 unpk2(ull v) {
    float2 f; asm("mov.b64 {%0, %1}, %2;" : "=f"(f.x), "=f"(f.y) : "l"(v)); return f;
}
__device__ __forceinline__ float fsig(float x)  { return __fdividef(1.f, 1.f + __expf(-x)); }
__device__ __forceinline__ float ftanh(float x) { return 2.f * __fdividef(1.f, 1.f + __expf(-2.f * x)) - 1.f; }

#define CLU_ARRIVE() asm volatile("barrier.cluster.arrive.aligned;" ::: "memory")
#define CLU_WAIT()   asm volatile("barrier.cluster.wait.aligned;"   ::: "memory")
#define FULLM 0xffffffffu

// 2-CTA cluster per batch; all W_hh register-resident; barrier.cluster sync
// (R8 skeleton) + REDUX argmax + packed local/peer publishes (R10 micro-opts).
__global__ void __cluster_dims__(2, 1, 1) __launch_bounds__(TPB, 1)
lstm_decoder_kernel(const float* __restrict__ h0,
                    const float* __restrict__ c0,
                    const float* __restrict__ tonehot,   // (TLEN+1, 1, OUTD)
                    const void*  __restrict__ tfraw,     // tf_mask (dtype autodetect)
                    const float* __restrict__ W_ih,      // (4*HID, OUTD)
                    const float* __restrict__ W_hh,      // (4*HID, HID)
                    const float* __restrict__ b_ih,
                    const float* __restrict__ b_hh,
                    const float* __restrict__ W_out,     // (OUTD, HID)
                    const float* __restrict__ b_out,
                    float* __restrict__ out)             // [143360 lp | 1280 hT | 1280 cT]
{
    __shared__ __align__(16) float h_s[2][HID];     // full h per CTA, parity buffered
    __shared__ float plog_s[2][16][8];              // warp logit partials: slot = rank*8+wid
    __shared__ float wih_s[4 * HID * OUTD];
    __shared__ int   tgt_s[TLEN];
    __shared__ unsigned char tf_s[TLEN];
    __shared__ float bout_s[OUTD];
    __shared__ int   tfmode_s;

    const int b    = blockIdx.x >> 1;    // batch
    const uint32_t rank = ctarank();     // 0 or 1
    const uint32_t peer = rank ^ 1u;
    const int tid  = threadIdx.x;
    const int lane = tid & 31;
    const int wid  = tid >> 5;           // 0..7
    const int ty   = tid & 3;            // gate type 0=i 1=f 2=g 3=o
    const int kl   = tid >> 2;           // local unit 0..63
    const int k    = (int)rank * KPC + kl;   // global hidden unit
    const int g    = ty * HID + k;           // gate row

    // Full W_hh row g in registers: 64 packed u64 (128 regs)
    ull wp[HID / 2];
#pragma unroll
    for (int i = 0; i < HID / 4; i++) {
        float4 v = reinterpret_cast<const float4*>(W_hh + (size_t)g * HID)[i];
        wp[2*i]   = pk2(v.x, v.y);
        wp[2*i+1] = pk2(v.z, v.w);
    }
    const float biasg = b_ih[g] + b_hh[g];
    const int   gbase = g * OUTD;

    const float wo1 = W_out[ty * HID + k];
    const float wo2 = (ty < 3) ? W_out[(ty + 4) * HID + k] : 0.f;

    float cval = c0[b * HID + k];

    // ---- init ----
    if (tid < HID) h_s[0][tid] = h0[b * HID + tid];
    for (int i = tid; i < 4 * HID * OUTD; i += TPB) wih_s[i] = W_ih[i];
    if (tid < OUTD) bout_s[tid] = b_out[tid];
    if (tid == 0) {                                   // tf dtype autodetect
        const int* ip = (const int*)tfraw;
        int mode = 0;
        for (int i = 0; i < 512; i++) {
            int v = ip[i];
            if (v == 0x3f800000) { mode = 1; break; }
            if (v != 0 && v != 1) mode = 2;
        }
        tfmode_s = mode;
    }
    __syncthreads();
    {
        const int mode = tfmode_s;
        for (int s = tid; s < TLEN; s += TPB) {
            unsigned char tv;
            if (mode == 0)      tv = ((const int*)tfraw)[s] != 0;
            else if (mode == 1) tv = ((const float*)tfraw)[s] != 0.f;
            else                tv = ((const unsigned char*)tfraw)[s] != 0;
            tf_s[s] = tv;
            const float* row = tonehot + (size_t)(s + 1) * OUTD;   // exactly one-hot
            int idx = 0; float best = row[0];
#pragma unroll
            for (int o = 1; o < OUTD; o++) { if (row[o] > best) { best = row[o]; idx = o; } }
            tgt_s[s] = idx;
        }
    }
    __syncthreads();
    CLU_ARRIVE(); CLU_WAIT();    // init visible cluster-wide

    // ================= main loop: one cluster.sync per step =================
    for (int t = 0; t < TLEN; t++) {
        const int p = t & 1;

        // ---- recurrent dot: all 128 cols, weights in regs, h broadcast-LDS ----
        ull acc0 = 0ull, acc1 = 0ull, acc2 = 0ull, acc3 = 0ull;
        const ulonglong2* hb = reinterpret_cast<const ulonglong2*>(h_s[p]);
#pragma unroll
        for (int i = 0; i < 16; i++) {
            ulonglong2 u = hb[2*i];
            ulonglong2 v = hb[2*i + 1];
            acc0 = fma2(u.x, wp[4*i],     acc0);
            acc1 = fma2(u.y, wp[4*i + 1], acc1);
            acc2 = fma2(v.x, wp[4*i + 2], acc2);
            acc3 = fma2(v.y, wp[4*i + 3], acc3);
        }

        // ---- argmax of logits(t-1) via single REDUX (exact, tie -> smallest idx) ----
        int xb = OUTD - 1;
        float slog = -1e30f, vmax = -1e30f;
        if (t > 0) {
            const int o = lane & 7;
            float s = -1e30f;
            uint32_t enc = 0;
            if (lane < 8 && o < OUTD) {
                const float* pp = &plog_s[p][0][o];
                float s0 = pp[0*8]  + pp[1*8];
                float s1 = pp[2*8]  + pp[3*8];
                float s2 = pp[4*8]  + pp[5*8];
                float s3 = pp[6*8]  + pp[7*8];
                float s4 = pp[8*8]  + pp[9*8];
                float s5 = pp[10*8] + pp[11*8];
                float s6 = pp[12*8] + pp[13*8];
                float s7 = pp[14*8] + pp[15*8];
                s = bout_s[o] + (((s0+s1)+(s2+s3)) + ((s4+s5)+(s6+s7)));
                // |s| small -> s+32 in (20,44): positive, monotone bit pattern
                enc = ((__float_as_uint(s + 32.0f) - 0x40000000u) << 3) | (uint32_t)(7 - o);
            }
            const uint32_t m = __reduce_max_sync(FULLM, enc);
            const int ia = 7 - (int)(m & 7u);
            vmax = __uint_as_float((m >> 3) + 0x40000000u) - 32.0f;
            slog = s;
            xb = tf_s[t - 1] ? tgt_s[t - 1] : ia;
        }

        // ---- finish gate ----
        float2 f0 = unpk2(acc0), f1 = unpk2(acc1), f2 = unpk2(acc2), f3 = unpk2(acc3);
        float vb = ((f0.x + f0.y) + (f1.x + f1.y)) + ((f2.x + f2.y) + (f3.x + f3.y))
                 + biasg + wih_s[gbase + xb];
        vb = (ty == 2) ? ftanh(vb) : fsig(vb);

        // ---- quad butterfly: every lane gets (i,f,g,o) of its unit ----
        const float pb1 = __shfl_xor_sync(FULLM, vb, 1, 4);
        const float ev  = (ty & 1) ? pb1 : vb;
        const float od  = (ty & 1) ? vb  : pb1;
        const float ev2 = __shfl_xor_sync(FULLM, ev, 2, 4);
        const float od2 = __shfl_xor_sync(FULLM, od, 2, 4);
        const float gi = (ty & 2) ? ev2 : ev;
        const float gf = (ty & 2) ? od2 : od;
        const float gg = (ty & 2) ? ev  : ev2;
        const float go = (ty & 2) ? od  : od2;

        // ---- pointwise (redundant x4 per unit) ----
        cval = gf * cval + gi * gg;
        const float h2 = go * ftanh(cval);

        // ---- h publish: packed 8B; local plain store + peer DSMEM ----
        const float h2hi = __shfl_xor_sync(FULLM, h2, 4);   // unit k^1 sits 4 lanes away
        if ((tid & 7) == 0) {                               // ty==0, k even
            const ull hv = pk2(h2, h2hi);
            *reinterpret_cast<ull*>(&h_s[p ^ 1][k]) = hv;
            dst_u64(sm2u(&h_s[p ^ 1][k]), peer, hv);
        }

        // ---- logit partials over the warp's 8 units ----
        float pl1 = h2 * wo1;
        float pl2 = h2 * wo2;
#pragma unroll
        for (int d = 4; d <= 16; d <<= 1) {
            pl1 += __shfl_xor_sync(FULLM, pl1, d);
            pl2 += __shfl_xor_sync(FULLM, pl2, d);
        }
        if (lane < 4) {
            const int slot = (int)rank * 8 + wid;
            plog_s[p ^ 1][slot][ty] = pl1;
            dst_f32(sm2u(&plog_s[p ^ 1][slot][ty]), peer, pl1);
            if (ty < 3) {
                plog_s[p ^ 1][slot][ty + 4] = pl2;
                dst_f32(sm2u(&plog_s[p ^ 1][slot][ty + 4]), peer, pl2);
            }
        }

        // ---- cluster sync; log-softmax(t-1)+STG inside the window ----
        CLU_ARRIVE();
        if (t > 0 && rank == 0 && wid == 7) {
            const int o = lane & 7;
            float e = (lane < 8 && o < OUTD) ? __expf(slog - vmax) : 0.f;
#pragma unroll
            for (int d = 4; d >= 1; d >>= 1)
                e += __shfl_xor_sync(FULLM, e, d, 8);
            const float lse = vmax + __logf(e);
            if (lane < OUTD)
                out[(size_t)b * TLEN * OUTD + (size_t)(t - 1) * OUTD + lane] = slog - lse;
        }
        CLU_WAIT();
    }

    // ================= epilogue =================
    {
        const int o = lane & 7;
        float s = -1e30f;
        if (lane < 8 && o < OUTD) {
            const float* pp = &plog_s[0][0][o];
            float acc = bout_s[o];
#pragma unroll
            for (int w2 = 0; w2 < 16; w2++) acc += pp[w2 * 8];
            s = acc;
        }
        float v = s;
#pragma unroll
        for (int d = 4; d >= 1; d >>= 1) {
            float v2 = __shfl_xor_sync(FULLM, v, d, 8);
            if (v2 > v) v = v2;
        }
        float e = (lane < 8 && o < OUTD) ? __expf(s - v) : 0.f;
#pragma unroll
        for (int d = 4; d >= 1; d >>= 1)
            e += __shfl_xor_sync(FULLM, e, d, 8);
        const float lse = v + __logf(e);
        if (rank == 0 && wid == 7 && lane < OUTD)
            out[(size_t)b * TLEN * OUTD + (size_t)(TLEN - 1) * OUTD + lane] = s - lse;

        if (rank == 0) {
            for (int i = tid; i < HID; i += TPB)
                out[(size_t)BATCHN * TLEN * OUTD + b * HID + i] = h_s[0][i];
        }
        if (ty == 0)
            out[(size_t)BATCHN * TLEN * OUTD + BATCHN * HID + b * HID + k] = cval;
    }
    // keep cluster alive until all peer-targeted DSMEM traffic is consumed
    CLU_ARRIVE(); CLU_WAIT();
}

extern "C" void kernel_launch(void* const* d_in, const int* in_sizes, int n_in,
                              void* d_out, int out_size) {
    (void)in_sizes; (void)n_in; (void)out_size;
    const float* h0    = (const float*)d_in[0];
    const float* c0    = (const float*)d_in[1];
    const float* toh   = (const float*)d_in[2];
    const void*  tf    = d_in[3];
    const float* W_ih  = (const float*)d_in[4];
    const float* W_hh  = (const float*)d_in[5];
    const float* b_ih  = (const float*)d_in[6];
    const float* b_hh  = (const float*)d_in[7];
    const float* W_out = (const float*)d_in[8];
    const float* b_out = (const float*)d_in[9];
    float* out = (float*)d_out;

    lstm_decoder_kernel<<<2 * BATCHN, TPB>>>(h0, c0, toh, tf, W_ih, W_hh,
                                             b_ih, b_hh, W_out, b_out, out);
}